// round 7
// baseline (speedup 1.0000x reference)
#include <cuda_runtime.h>
#include <cstdint>

#define DIM   64
#define NPAD  53248          // 1024 * 52 (>= N, padded for single-block scan)
#define EMAX  800000

// Scratch (allocation-free rule: __device__ globals).
// g_deg is zero on first call (static init) and re-zeroed by k_gather every
// launch after consumption -> invariant holds across graph replays.
__device__ int   g_deg[NPAD];
__device__ int   g_start[NPAD];
__device__ int   g_cursor[NPAD];
__device__ int   g_cols[EMAX];
__device__ float g_agg[(size_t)NPAD * DIM];   // normalized row sums

// ---------------------------------------------------------------------------
// 1. histogram of destination rows (4 edges per thread, int4 reads)
// ---------------------------------------------------------------------------
__global__ __launch_bounds__(256) void k_hist(const int* __restrict__ ei, int E) {
    int i = (blockIdx.x * blockDim.x + threadIdx.x) * 4;
    if (i + 3 < E) {
        int4 r = *(const int4*)(ei + i);
        atomicAdd(&g_deg[r.x], 1);
        atomicAdd(&g_deg[r.y], 1);
        atomicAdd(&g_deg[r.z], 1);
        atomicAdd(&g_deg[r.w], 1);
    } else {
        for (int k = i; k < E; k++) atomicAdd(&g_deg[ei[k]], 1);
    }
}

// ---------------------------------------------------------------------------
// 2. single-block exclusive scan over all NPAD degrees -> start, cursor.
// ---------------------------------------------------------------------------
__global__ __launch_bounds__(1024) void k_scan() {
    __shared__ int s[1024];
    int tid = threadIdx.x;
    const int4* dv = (const int4*)g_deg + tid * 13;

    int tot = 0;
    int4 loc[13];
    #pragma unroll
    for (int i = 0; i < 13; i++) {
        loc[i] = dv[i];
        tot += loc[i].x + loc[i].y + loc[i].z + loc[i].w;
    }
    s[tid] = tot;
    __syncthreads();
    #pragma unroll
    for (int off = 1; off < 1024; off <<= 1) {
        int t = (tid >= off) ? s[tid - off] : 0;
        __syncthreads();
        s[tid] += t;
        __syncthreads();
    }
    int run = s[tid] - tot;     // exclusive prefix of this thread's chunk

    int4* sv = (int4*)g_start  + tid * 13;
    int4* cv = (int4*)g_cursor + tid * 13;
    #pragma unroll
    for (int i = 0; i < 13; i++) {
        int4 v = loc[i];
        int4 o;
        o.x = run; run += v.x;
        o.y = run; run += v.y;
        o.z = run; run += v.z;
        o.w = run; run += v.w;
        sv[i] = o;
        cv[i] = o;
    }
}

// ---------------------------------------------------------------------------
// 3. scatter source cols into CSR order (4 edges per thread, int4 reads)
// ---------------------------------------------------------------------------
__global__ __launch_bounds__(256) void k_scatter(const int* __restrict__ ei, int E) {
    int i = (blockIdx.x * blockDim.x + threadIdx.x) * 4;
    if (i + 3 < E) {
        int4 r = *(const int4*)(ei + i);
        int4 c = *(const int4*)(ei + E + i);
        g_cols[atomicAdd(&g_cursor[r.x], 1)] = c.x;
        g_cols[atomicAdd(&g_cursor[r.y], 1)] = c.y;
        g_cols[atomicAdd(&g_cursor[r.z], 1)] = c.z;
        g_cols[atomicAdd(&g_cursor[r.w], 1)] = c.w;
    } else {
        for (int k = i; k < E; k++)
            g_cols[atomicAdd(&g_cursor[ei[k]], 1)] = ei[E + k];
    }
}

// ---------------------------------------------------------------------------
// 4. gather: ONE WARP PER ROW, paired edges (uniform iteration count).
//    Lanes split into 2 groups of 16 (g = lane>>4); group g handles edges
//    j+g, j+g+2, ... ; each lane loads one float4 chunk (t = lane&15).
//    Half-warp partials combined via shfl_xor(16). Normalized store + deg reset.
//    No smem, low regs -> full occupancy for latency hiding.
// ---------------------------------------------------------------------------
__global__ __launch_bounds__(256) void k_gather(const float* __restrict__ x, int n) {
    int warp = (blockIdx.x * 256 + threadIdx.x) >> 5;
    int lane = threadIdx.x & 31;
    int row  = warp;
    if (row >= n) return;

    const int g = lane >> 4;      // half-warp group
    const int t = lane & 15;      // float4 chunk

    int s0 = g_start[row];
    int c  = g_deg[row];
    if (lane == 0) g_deg[row] = 0;   // reset for next launch (c already read)

    float4 acc = make_float4(0.f, 0.f, 0.f, 0.f);
    int j = 0;
    // main loop: 8 edges per iteration across the warp (4 per group)
    for (; j + 8 <= c; j += 8) {
        int i0 = s0 + j + g;
        int c0 = g_cols[i0];
        int c1 = g_cols[i0 + 2];
        int c2 = g_cols[i0 + 4];
        int c3 = g_cols[i0 + 6];
        float4 v0 = *(const float4*)(x + (size_t)c0 * DIM + t * 4);
        float4 v1 = *(const float4*)(x + (size_t)c1 * DIM + t * 4);
        float4 v2 = *(const float4*)(x + (size_t)c2 * DIM + t * 4);
        float4 v3 = *(const float4*)(x + (size_t)c3 * DIM + t * 4);
        acc.x += v0.x + v1.x + v2.x + v3.x;
        acc.y += v0.y + v1.y + v2.y + v3.y;
        acc.z += v0.z + v1.z + v2.z + v3.z;
        acc.w += v0.w + v1.w + v2.w + v3.w;
    }
    // pair tail
    for (; j + 2 <= c; j += 2) {
        int cc = g_cols[s0 + j + g];
        float4 v = *(const float4*)(x + (size_t)cc * DIM + t * 4);
        acc.x += v.x; acc.y += v.y; acc.z += v.z; acc.w += v.w;
    }
    // odd edge: group 0 only
    if (j < c && g == 0) {
        int cc = g_cols[s0 + j];
        float4 v = *(const float4*)(x + (size_t)cc * DIM + t * 4);
        acc.x += v.x; acc.y += v.y; acc.z += v.z; acc.w += v.w;
    }

    // combine half-warp partials (lane t <-> lane t+16 hold the same chunk)
    acc.x += __shfl_xor_sync(0xffffffff, acc.x, 16);
    acc.y += __shfl_xor_sync(0xffffffff, acc.y, 16);
    acc.z += __shfl_xor_sync(0xffffffff, acc.z, 16);
    acc.w += __shfl_xor_sync(0xffffffff, acc.w, 16);

    if (g == 0) {
        float inv = 1.0f / ((float)c + 1e-6f);
        acc.x *= inv; acc.y *= inv; acc.z *= inv; acc.w *= inv;
        *(float4*)&g_agg[(size_t)row * DIM + t * 4] = acc;
    }
}

// ---------------------------------------------------------------------------
// 5. out = agg @ W^T + b   (agg already normalized)
// ---------------------------------------------------------------------------
__global__ __launch_bounds__(256) void out_kernel(
    const float* __restrict__ W,
    const float* __restrict__ b,
    float* __restrict__ out,
    int n)
{
    __shared__ float sW[64 * 68];
    __shared__ float sA[64 * 68];
    __shared__ float sB[64];

    const int tid  = threadIdx.x;
    const int base = blockIdx.x * 64;

    for (int idx = tid; idx < 64 * 64; idx += 256) {
        int j = idx >> 6;
        int k = idx & 63;
        sW[k * 68 + j] = W[idx];
    }
    if (tid < 64) sB[tid] = b[tid];

    #pragma unroll
    for (int p = 0; p < 4; p++) {
        int idx  = tid + p * 256;
        int nd   = idx >> 4;
        int ch   = idx & 15;
        int node = base + nd;
        float4 v = make_float4(0.f, 0.f, 0.f, 0.f);
        if (node < n)
            v = *(const float4*)&g_agg[(size_t)node * DIM + ch * 4];
        *(float4*)&sA[nd * 68 + ch * 4] = v;
    }
    __syncthreads();

    const int tx = tid & 15;
    const int ty = tid >> 4;

    float acc[4][4];
    #pragma unroll
    for (int i = 0; i < 4; i++)
        #pragma unroll
        for (int c = 0; c < 4; c++)
            acc[i][c] = 0.f;

    #pragma unroll
    for (int k = 0; k < 64; k += 4) {
        float4 wv0 = *(const float4*)&sW[(k + 0) * 68 + tx * 4];
        float4 wv1 = *(const float4*)&sW[(k + 1) * 68 + tx * 4];
        float4 wv2 = *(const float4*)&sW[(k + 2) * 68 + tx * 4];
        float4 wv3 = *(const float4*)&sW[(k + 3) * 68 + tx * 4];
        #pragma unroll
        for (int i = 0; i < 4; i++) {
            float4 av = *(const float4*)&sA[(ty * 4 + i) * 68 + k];
            acc[i][0] += av.x * wv0.x + av.y * wv1.x + av.z * wv2.x + av.w * wv3.x;
            acc[i][1] += av.x * wv0.y + av.y * wv1.y + av.z * wv2.y + av.w * wv3.y;
            acc[i][2] += av.x * wv0.z + av.y * wv1.z + av.z * wv2.z + av.w * wv3.z;
            acc[i][3] += av.x * wv0.w + av.y * wv1.w + av.z * wv2.w + av.w * wv3.w;
        }
    }

    #pragma unroll
    for (int i = 0; i < 4; i++) {
        int node = base + ty * 4 + i;
        if (node < n) {
            float4 o;
            o.x = acc[i][0] + sB[tx * 4 + 0];
            o.y = acc[i][1] + sB[tx * 4 + 1];
            o.z = acc[i][2] + sB[tx * 4 + 2];
            o.w = acc[i][3] + sB[tx * 4 + 3];
            *(float4*)&out[(size_t)node * DIM + tx * 4] = o;
        }
    }
}

// ---------------------------------------------------------------------------
// kernel_launch — inputs: x [N*64 f32], edge_index [2*E i32], W [64*64 f32],
// b [64 f32]; output [N*64 f32].
// ---------------------------------------------------------------------------
extern "C" void kernel_launch(void* const* d_in, const int* in_sizes, int n_in,
                              void* d_out, int out_size) {
    const float* x  = (const float*)d_in[0];
    const int*   ei = (const int*)d_in[1];
    const float* W  = (const float*)d_in[2];
    const float* b  = (const float*)d_in[3];
    float*       out = (float*)d_out;

    int n = in_sizes[0] / DIM;       // 50000
    int E = in_sizes[1] / 2;         // 800000

    int eblocks = (E / 4 + 255) / 256 + 1;

    k_hist<<<eblocks, 256>>>(ei, E);
    k_scan<<<1, 1024>>>();
    k_scatter<<<eblocks, 256>>>(ei, E);
    k_gather<<<(n + 7) / 8, 256>>>(x, n);
    out_kernel<<<(n + 63) / 64, 256>>>(W, b, out, n);
}

// round 8
// speedup vs baseline: 1.3951x; 1.3951x over previous
#include <cuda_runtime.h>
#include <cstdint>

#define DIM   64
#define NPAD  53248          // 1024 * 52 (>= N, padded for single-block scan)
#define EMAX  800000

// Scratch (allocation-free rule: __device__ globals).
// g_deg is zero on first call (static init) and re-zeroed by k_gather every
// launch after consumption -> invariant holds across graph replays.
__device__ int   g_deg[NPAD];
__device__ int   g_start[NPAD];
__device__ int   g_cursor[NPAD];
__device__ int   g_cols[EMAX];
__device__ float g_agg[(size_t)NPAD * DIM];   // normalized row sums

// ---------------------------------------------------------------------------
// 1. histogram of destination rows (4 edges per thread, int4 reads)
// ---------------------------------------------------------------------------
__global__ __launch_bounds__(256) void k_hist(const int* __restrict__ ei, int E) {
    int i = (blockIdx.x * blockDim.x + threadIdx.x) * 4;
    if (i + 3 < E) {
        int4 r = *(const int4*)(ei + i);
        atomicAdd(&g_deg[r.x], 1);
        atomicAdd(&g_deg[r.y], 1);
        atomicAdd(&g_deg[r.z], 1);
        atomicAdd(&g_deg[r.w], 1);
    } else {
        for (int k = i; k < E; k++) atomicAdd(&g_deg[ei[k]], 1);
    }
}

// ---------------------------------------------------------------------------
// 2. single-block exclusive scan over all NPAD degrees -> start, cursor.
// ---------------------------------------------------------------------------
__global__ __launch_bounds__(1024) void k_scan() {
    __shared__ int s[1024];
    int tid = threadIdx.x;
    const int4* dv = (const int4*)g_deg + tid * 13;

    int tot = 0;
    int4 loc[13];
    #pragma unroll
    for (int i = 0; i < 13; i++) {
        loc[i] = dv[i];
        tot += loc[i].x + loc[i].y + loc[i].z + loc[i].w;
    }
    s[tid] = tot;
    __syncthreads();
    #pragma unroll
    for (int off = 1; off < 1024; off <<= 1) {
        int t = (tid >= off) ? s[tid - off] : 0;
        __syncthreads();
        s[tid] += t;
        __syncthreads();
    }
    int run = s[tid] - tot;     // exclusive prefix of this thread's chunk

    int4* sv = (int4*)g_start  + tid * 13;
    int4* cv = (int4*)g_cursor + tid * 13;
    #pragma unroll
    for (int i = 0; i < 13; i++) {
        int4 v = loc[i];
        int4 o;
        o.x = run; run += v.x;
        o.y = run; run += v.y;
        o.z = run; run += v.z;
        o.w = run; run += v.w;
        sv[i] = o;
        cv[i] = o;
    }
}

// ---------------------------------------------------------------------------
// 3. scatter source cols into CSR order (4 edges per thread, int4 reads)
// ---------------------------------------------------------------------------
__global__ __launch_bounds__(256) void k_scatter(const int* __restrict__ ei, int E) {
    int i = (blockIdx.x * blockDim.x + threadIdx.x) * 4;
    if (i + 3 < E) {
        int4 r = *(const int4*)(ei + i);
        int4 c = *(const int4*)(ei + E + i);
        g_cols[atomicAdd(&g_cursor[r.x], 1)] = c.x;
        g_cols[atomicAdd(&g_cursor[r.y], 1)] = c.y;
        g_cols[atomicAdd(&g_cursor[r.z], 1)] = c.z;
        g_cols[atomicAdd(&g_cursor[r.w], 1)] = c.w;
    } else {
        for (int k = i; k < E; k++)
            g_cols[atomicAdd(&g_cursor[ei[k]], 1)] = ei[E + k];
    }
}

// ---------------------------------------------------------------------------
// 4. gather-sum (R4-proven pattern): 16 threads per row, float4 accumulators,
//    4-edge unroll. Normalization + deg reset folded in. No smem, low regs.
// ---------------------------------------------------------------------------
__global__ __launch_bounds__(256) void k_gather(const float* __restrict__ x, int n) {
    int row = blockIdx.x * 16 + (threadIdx.x >> 4);
    int t   = threadIdx.x & 15;
    if (row >= n) return;

    int s = g_start[row];
    int c = g_deg[row];
    if (t == 0) g_deg[row] = 0;   // reset for next replay (c already read by all lanes)

    float4 acc = make_float4(0.f, 0.f, 0.f, 0.f);
    int j = 0;
    for (; j + 4 <= c; j += 4) {
        int c0 = g_cols[s + j + 0];
        int c1 = g_cols[s + j + 1];
        int c2 = g_cols[s + j + 2];
        int c3 = g_cols[s + j + 3];
        float4 v0 = *(const float4*)(x + (size_t)c0 * DIM + t * 4);
        float4 v1 = *(const float4*)(x + (size_t)c1 * DIM + t * 4);
        float4 v2 = *(const float4*)(x + (size_t)c2 * DIM + t * 4);
        float4 v3 = *(const float4*)(x + (size_t)c3 * DIM + t * 4);
        acc.x += v0.x + v1.x + v2.x + v3.x;
        acc.y += v0.y + v1.y + v2.y + v3.y;
        acc.z += v0.z + v1.z + v2.z + v3.z;
        acc.w += v0.w + v1.w + v2.w + v3.w;
    }
    for (; j < c; j++) {
        int cc = g_cols[s + j];
        float4 v = *(const float4*)(x + (size_t)cc * DIM + t * 4);
        acc.x += v.x; acc.y += v.y; acc.z += v.z; acc.w += v.w;
    }

    float inv = 1.0f / ((float)c + 1e-6f);
    acc.x *= inv; acc.y *= inv; acc.z *= inv; acc.w *= inv;
    *(float4*)&g_agg[(size_t)row * DIM + t * 4] = acc;
}

// ---------------------------------------------------------------------------
// 5. out = agg @ W^T + b   (agg already normalized)
// ---------------------------------------------------------------------------
__global__ __launch_bounds__(256) void out_kernel(
    const float* __restrict__ W,
    const float* __restrict__ b,
    float* __restrict__ out,
    int n)
{
    __shared__ float sW[64 * 68];
    __shared__ float sA[64 * 68];
    __shared__ float sB[64];

    const int tid  = threadIdx.x;
    const int base = blockIdx.x * 64;

    for (int idx = tid; idx < 64 * 64; idx += 256) {
        int j = idx >> 6;
        int k = idx & 63;
        sW[k * 68 + j] = W[idx];
    }
    if (tid < 64) sB[tid] = b[tid];

    #pragma unroll
    for (int p = 0; p < 4; p++) {
        int idx  = tid + p * 256;
        int nd   = idx >> 4;
        int ch   = idx & 15;
        int node = base + nd;
        float4 v = make_float4(0.f, 0.f, 0.f, 0.f);
        if (node < n)
            v = *(const float4*)&g_agg[(size_t)node * DIM + ch * 4];
        *(float4*)&sA[nd * 68 + ch * 4] = v;
    }
    __syncthreads();

    const int tx = tid & 15;
    const int ty = tid >> 4;

    float acc[4][4];
    #pragma unroll
    for (int i = 0; i < 4; i++)
        #pragma unroll
        for (int c = 0; c < 4; c++)
            acc[i][c] = 0.f;

    #pragma unroll
    for (int k = 0; k < 64; k += 4) {
        float4 wv0 = *(const float4*)&sW[(k + 0) * 68 + tx * 4];
        float4 wv1 = *(const float4*)&sW[(k + 1) * 68 + tx * 4];
        float4 wv2 = *(const float4*)&sW[(k + 2) * 68 + tx * 4];
        float4 wv3 = *(const float4*)&sW[(k + 3) * 68 + tx * 4];
        #pragma unroll
        for (int i = 0; i < 4; i++) {
            float4 av = *(const float4*)&sA[(ty * 4 + i) * 68 + k];
            acc[i][0] += av.x * wv0.x + av.y * wv1.x + av.z * wv2.x + av.w * wv3.x;
            acc[i][1] += av.x * wv0.y + av.y * wv1.y + av.z * wv2.y + av.w * wv3.y;
            acc[i][2] += av.x * wv0.z + av.y * wv1.z + av.z * wv2.z + av.w * wv3.z;
            acc[i][3] += av.x * wv0.w + av.y * wv1.w + av.z * wv2.w + av.w * wv3.w;
        }
    }

    #pragma unroll
    for (int i = 0; i < 4; i++) {
        int node = base + ty * 4 + i;
        if (node < n) {
            float4 o;
            o.x = acc[i][0] + sB[tx * 4 + 0];
            o.y = acc[i][1] + sB[tx * 4 + 1];
            o.z = acc[i][2] + sB[tx * 4 + 2];
            o.w = acc[i][3] + sB[tx * 4 + 3];
            *(float4*)&out[(size_t)node * DIM + tx * 4] = o;
        }
    }
}

// ---------------------------------------------------------------------------
// kernel_launch — inputs: x [N*64 f32], edge_index [2*E i32], W [64*64 f32],
// b [64 f32]; output [N*64 f32].
// ---------------------------------------------------------------------------
extern "C" void kernel_launch(void* const* d_in, const int* in_sizes, int n_in,
                              void* d_out, int out_size) {
    const float* x  = (const float*)d_in[0];
    const int*   ei = (const int*)d_in[1];
    const float* W  = (const float*)d_in[2];
    const float* b  = (const float*)d_in[3];
    float*       out = (float*)d_out;

    int n = in_sizes[0] / DIM;       // 50000
    int E = in_sizes[1] / 2;         // 800000

    int eblocks = (E / 4 + 255) / 256 + 1;

    k_hist<<<eblocks, 256>>>(ei, E);
    k_scan<<<1, 1024>>>();
    k_scatter<<<eblocks, 256>>>(ei, E);
    k_gather<<<(n + 15) / 16, 256>>>(x, n);
    out_kernel<<<(n + 63) / 64, 256>>>(W, b, out, n);
}